// round 2
// baseline (speedup 1.0000x reference)
#include <cuda_runtime.h>
#include <cuda_bf16.h>

// Shapes (compile-time)
#define T_    512
#define C_    768
#define KVC_  384
#define NH_   12
#define NKV_  6
#define HD_   64
#define HALF_ 32

// ---------------- scratch (device globals: no allocs allowed) ----------------
__device__ float g_q[T_ * C_];          // x@Wq  (t, h*64+d)
__device__ float g_k[T_ * KVC_];        // x@Wk
__device__ float g_v[T_ * KVC_];        // x@Wv
__device__ float g_Q[NH_ * T_ * HD_];   // head-major, rope+rmsnormed
__device__ float g_K[NKV_ * T_ * HD_];
__device__ float g_V[NKV_ * T_ * HD_];
__device__ float g_Y[T_ * C_];          // attention output (t, h*64+d)

// ---------------- tiled fp32 GEMM: C[M,N] = A[M,K] @ B[K,N] ------------------
// BM=BN=64, BK=16, 256 threads, 4x4 micro-tile per thread.
// All dims assumed multiples of tile sizes (true for this problem).
#define BM 64
#define BN 64
#define BK 16

__device__ __forceinline__ void gemm_tile(const float* __restrict__ A, int lda,
                                          const float* __restrict__ B, int ldb,
                                          float* __restrict__ C, int ldc,
                                          int m0, int n0, int K) {
    __shared__ float As[BK][BM + 1];   // +1 pad: conflict-free transposed stores
    __shared__ float Bs[BK][BN];

    const int tid = threadIdx.x;
    const int tx = tid & 15;          // 0..15 -> 4 output cols each
    const int ty = tid >> 4;          // 0..15 -> 4 output rows each

    const int aRow = tid >> 2;        // 0..63
    const int aCol = (tid & 3) * 4;   // 0,4,8,12
    const int bRow = tid >> 4;        // 0..15
    const int bCol = (tid & 15) * 4;  // 0..60

    float acc[4][4] = {};

    for (int k0 = 0; k0 < K; k0 += BK) {
        float4 av = *(const float4*)(A + (size_t)(m0 + aRow) * lda + k0 + aCol);
        float4 bv = *(const float4*)(B + (size_t)(k0 + bRow) * ldb + n0 + bCol);
        __syncthreads();   // previous iteration's compute done before overwrite
        As[aCol + 0][aRow] = av.x;
        As[aCol + 1][aRow] = av.y;
        As[aCol + 2][aRow] = av.z;
        As[aCol + 3][aRow] = av.w;
        *(float4*)&Bs[bRow][bCol] = bv;
        __syncthreads();
#pragma unroll
        for (int k = 0; k < BK; k++) {
            float a0 = As[k][ty * 4 + 0];
            float a1 = As[k][ty * 4 + 1];
            float a2 = As[k][ty * 4 + 2];
            float a3 = As[k][ty * 4 + 3];
            float4 b = *(const float4*)&Bs[k][tx * 4];
            acc[0][0] += a0 * b.x; acc[0][1] += a0 * b.y; acc[0][2] += a0 * b.z; acc[0][3] += a0 * b.w;
            acc[1][0] += a1 * b.x; acc[1][1] += a1 * b.y; acc[1][2] += a1 * b.z; acc[1][3] += a1 * b.w;
            acc[2][0] += a2 * b.x; acc[2][1] += a2 * b.y; acc[2][2] += a2 * b.z; acc[2][3] += a2 * b.w;
            acc[3][0] += a3 * b.x; acc[3][1] += a3 * b.y; acc[3][2] += a3 * b.z; acc[3][3] += a3 * b.w;
        }
    }

#pragma unroll
    for (int i = 0; i < 4; i++) {
        float4 out = make_float4(acc[i][0], acc[i][1], acc[i][2], acc[i][3]);
        *(float4*)(C + (size_t)(m0 + ty * 4 + i) * ldc + n0 + tx * 4) = out;
    }
}

// ---------------- kernel 1: fused QKV GEMM -----------------------------------
// Output columns [0,768) -> g_q, [768,1152) -> g_k, [1152,1536) -> g_v
__global__ void qkv_gemm_kernel(const float* __restrict__ x,
                                const float* __restrict__ Wq,
                                const float* __restrict__ Wk,
                                const float* __restrict__ Wv) {
    int n0 = blockIdx.x * BN;
    int m0 = blockIdx.y * BM;
    const float* B;
    float* Cp;
    int ldb, ldc, noff;
    if (n0 < C_)              { B = Wq; Cp = g_q; ldb = C_;   ldc = C_;   noff = n0; }
    else if (n0 < C_ + KVC_)  { B = Wk; Cp = g_k; ldb = KVC_; ldc = KVC_; noff = n0 - C_; }
    else                      { B = Wv; Cp = g_v; ldb = KVC_; ldc = KVC_; noff = n0 - C_ - KVC_; }
    gemm_tile(x, C_, B, ldb, Cp, ldc, m0, noff, C_);
}

// ---------------- kernel 2: RoPE + RMSNorm + head transpose ------------------
// One block per token t, 8 warps, warp handles tasks {w, w+8, w+16} of 24
// tasks: 12 Q heads, 6 K heads, 6 V copies. Lane l owns dims l and l+32
// (exactly the rope pair).
__global__ void rope_norm_kernel(const float* __restrict__ cosp,
                                 const float* __restrict__ sinp) {
    int t = blockIdx.x;
    int warp = threadIdx.x >> 5;
    int lane = threadIdx.x & 31;
    float c = cosp[t * HALF_ + lane];
    float s = sinp[t * HALF_ + lane];

    for (int task = warp; task < 24; task += 8) {
        if (task < NH_) {                   // Q head
            int h = task;
            const float* src = g_q + (size_t)t * C_ + h * HD_;
            float x1 = src[lane], x2 = src[lane + HALF_];
            float o1 = x1 * c - x2 * s;
            float o2 = x2 * c + x1 * s;
            float ss = o1 * o1 + o2 * o2;
#pragma unroll
            for (int o = 16; o; o >>= 1) ss += __shfl_xor_sync(0xffffffffu, ss, o);
            float r = rsqrtf(ss * (1.0f / HD_) + 1e-6f);
            float* dst = g_Q + ((size_t)h * T_ + t) * HD_;
            dst[lane] = o1 * r;
            dst[lane + HALF_] = o2 * r;
        } else if (task < NH_ + NKV_) {     // K head
            int h = task - NH_;
            const float* src = g_k + (size_t)t * KVC_ + h * HD_;
            float x1 = src[lane], x2 = src[lane + HALF_];
            float o1 = x1 * c - x2 * s;
            float o2 = x2 * c + x1 * s;
            float ss = o1 * o1 + o2 * o2;
#pragma unroll
            for (int o = 16; o; o >>= 1) ss += __shfl_xor_sync(0xffffffffu, ss, o);
            float r = rsqrtf(ss * (1.0f / HD_) + 1e-6f);
            float* dst = g_K + ((size_t)h * T_ + t) * HD_;
            dst[lane] = o1 * r;
            dst[lane + HALF_] = o2 * r;
        } else {                            // V: plain head-major copy
            int h = task - NH_ - NKV_;
            const float* src = g_v + (size_t)t * KVC_ + h * HD_;
            float* dst = g_V + ((size_t)h * T_ + t) * HD_;
            dst[lane] = src[lane];
            dst[lane + HALF_] = src[lane + HALF_];
        }
    }
}

// ---------------- kernel 3: tropical attention (warp per query) --------------
// scores[i,j] = max_d(q_d + k_d); causal; online softmax; acc += w * v.
__global__ void attn_kernel() {
    int gw = (blockIdx.x * blockDim.x + threadIdx.x) >> 5;
    int lane = threadIdx.x & 31;
    if (gw >= NH_ * T_) return;
    int h = gw / T_;
    int qi = gw % T_;
    int kv = h >> 1;   // n_rep = 2

    const float* Qp = g_Q + ((size_t)h * T_ + qi) * HD_;
    float q0 = Qp[lane];
    float q1 = Qp[lane + HALF_];

    const float* Kb = g_K + (size_t)kv * T_ * HD_;
    const float* Vb = g_V + (size_t)kv * T_ * HD_;

    float m = -1e30f, l = 0.0f, a0 = 0.0f, a1 = 0.0f;
    for (int j = 0; j <= qi; j++) {
        const float* Kp = Kb + (size_t)j * HD_;
        float sl = fmaxf(q0 + Kp[lane], q1 + Kp[lane + HALF_]);
#pragma unroll
        for (int o = 16; o; o >>= 1) sl = fmaxf(sl, __shfl_xor_sync(0xffffffffu, sl, o));
        float mn = fmaxf(m, sl);
        float corr = __expf(m - mn);     // m=-1e30 on first iter -> underflows to 0
        float w = __expf(sl - mn);
        const float* Vp = Vb + (size_t)j * HD_;
        a0 = a0 * corr + w * Vp[lane];
        a1 = a1 * corr + w * Vp[lane + HALF_];
        l = l * corr + w;
        m = mn;
    }
    float inv = 1.0f / l;
    float* Yp = g_Y + (size_t)qi * C_ + h * HD_;
    Yp[lane] = a0 * inv;
    Yp[lane + HALF_] = a1 * inv;
}

// ---------------- kernel 4: output projection --------------------------------
__global__ void proj_gemm_kernel(const float* __restrict__ Wp,
                                 float* __restrict__ out) {
    gemm_tile(g_Y, C_, Wp, C_, out, C_, blockIdx.y * BM, blockIdx.x * BN, C_);
}

// ---------------- launch -----------------------------------------------------
extern "C" void kernel_launch(void* const* d_in, const int* in_sizes, int n_in,
                              void* d_out, int out_size) {
    const float* x    = (const float*)d_in[0];
    const float* cosp = (const float*)d_in[1];
    const float* sinp = (const float*)d_in[2];
    const float* Wq   = (const float*)d_in[3];
    const float* Wk   = (const float*)d_in[4];
    const float* Wv   = (const float*)d_in[5];
    const float* Wp   = (const float*)d_in[6];
    float* out = (float*)d_out;

    // 1) QKV: 512 x (768|384|384), K=768. Grid: 24 col-tiles x 8 row-tiles.
    qkv_gemm_kernel<<<dim3((C_ + 2 * KVC_) / BN, T_ / BM), 256>>>(x, Wq, Wk, Wv);
    // 2) RoPE + RMSNorm + transpose to head-major
    rope_norm_kernel<<<T_, 256>>>(cosp, sinp);
    // 3) Tropical flash attention: 12*512 warps, 8 warps/block
    attn_kernel<<<(NH_ * T_ * 32 + 255) / 256, 256>>>();
    // 4) Projection: 512x768 @ 768x768
    proj_gemm_kernel<<<dim3(C_ / BN, T_ / BM), 256>>>(Wp, out);
}

// round 6
// speedup vs baseline: 1.8025x; 1.8025x over previous
#include <cuda_runtime.h>
#include <cuda_bf16.h>

// Shapes (compile-time)
#define T_    512
#define C_    768
#define KVC_  384
#define NH_   12
#define NKV_  6
#define HD_   64
#define HALF_ 32

// ---------------- scratch (device globals: no allocs allowed) ----------------
__device__ float g_q[T_ * C_];          // x@Wq  (t, h*64+d)
__device__ float g_k[T_ * KVC_];        // x@Wk
__device__ float g_v[T_ * KVC_];        // x@Wv
__device__ float g_Q[NH_ * T_ * HD_];   // head-major, rope+rmsnormed
__device__ float g_K[NKV_ * T_ * HD_];
__device__ float g_V[NKV_ * T_ * HD_];
__device__ float g_Y[T_ * C_];          // attention output (t, h*64+d)

// ---------------- zero-init for split-K atomic accumulation ------------------
__global__ void zero_kernel(float* out) {
    int i = blockIdx.x * blockDim.x + threadIdx.x;
    if (i < T_ * C_) { g_q[i] = 0.0f; out[i] = 0.0f; }
    if (i < T_ * KVC_) { g_k[i] = 0.0f; g_v[i] = 0.0f; }
}

// ---------------- fp32 GEMM tile: 64x64, BK=16, 128 threads, 8x4 micro -------
// FMA-bound design: per k-step each thread does 32 FMA for 48B of LDS traffic.
// Split-K partials are accumulated with atomicAdd (2-way: bit-deterministic).
#define GBM 64
#define GBN 64
#define GBK 16

__device__ __forceinline__ void gemm_tile_atomic(
        const float* __restrict__ A, int lda,
        const float* __restrict__ B, int ldb,
        float* __restrict__ C, int ldc,
        int m0, int n0, int k_begin, int k_end) {
    __shared__ float As[GBK][GBM + 4];   // transposed A, padded
    __shared__ float Bs[GBK][GBN];

    const int tid = threadIdx.x;
    const int tx = tid & 15;          // 16 col groups * 4 cols
    const int ty = tid >> 4;          // 8 row groups * 8 rows

    float acc[8][4] = {};

    for (int k0 = k_begin; k0 < k_end; k0 += GBK) {
        float4 av[2], bv[2];
#pragma unroll
        for (int i = 0; i < 2; i++) {
            int f = tid + i * 128;
            int ar = f >> 2, ac = (f & 3) * 4;
            av[i] = *(const float4*)(A + (size_t)(m0 + ar) * lda + k0 + ac);
            int br = f >> 4, bc = (f & 15) * 4;
            bv[i] = *(const float4*)(B + (size_t)(k0 + br) * ldb + n0 + bc);
        }
        __syncthreads();   // previous iteration's compute done before overwrite
#pragma unroll
        for (int i = 0; i < 2; i++) {
            int f = tid + i * 128;
            int ar = f >> 2, ac = (f & 3) * 4;
            As[ac + 0][ar] = av[i].x;
            As[ac + 1][ar] = av[i].y;
            As[ac + 2][ar] = av[i].z;
            As[ac + 3][ar] = av[i].w;
            int br = f >> 4, bc = (f & 15) * 4;
            *(float4*)&Bs[br][bc] = bv[i];
        }
        __syncthreads();
#pragma unroll
        for (int k = 0; k < GBK; k++) {
            float4 a0 = *(const float4*)&As[k][ty * 8];
            float4 a1 = *(const float4*)&As[k][ty * 8 + 4];
            float4 b  = *(const float4*)&Bs[k][tx * 4];
            acc[0][0] += a0.x * b.x; acc[0][1] += a0.x * b.y; acc[0][2] += a0.x * b.z; acc[0][3] += a0.x * b.w;
            acc[1][0] += a0.y * b.x; acc[1][1] += a0.y * b.y; acc[1][2] += a0.y * b.z; acc[1][3] += a0.y * b.w;
            acc[2][0] += a0.z * b.x; acc[2][1] += a0.z * b.y; acc[2][2] += a0.z * b.z; acc[2][3] += a0.z * b.w;
            acc[3][0] += a0.w * b.x; acc[3][1] += a0.w * b.y; acc[3][2] += a0.w * b.z; acc[3][3] += a0.w * b.w;
            acc[4][0] += a1.x * b.x; acc[4][1] += a1.x * b.y; acc[4][2] += a1.x * b.z; acc[4][3] += a1.x * b.w;
            acc[5][0] += a1.y * b.x; acc[5][1] += a1.y * b.y; acc[5][2] += a1.y * b.z; acc[5][3] += a1.y * b.w;
            acc[6][0] += a1.z * b.x; acc[6][1] += a1.z * b.y; acc[6][2] += a1.z * b.z; acc[6][3] += a1.z * b.w;
            acc[7][0] += a1.w * b.x; acc[7][1] += a1.w * b.y; acc[7][2] += a1.w * b.z; acc[7][3] += a1.w * b.w;
        }
    }

#pragma unroll
    for (int i = 0; i < 8; i++) {
        float* Cr = C + (size_t)(m0 + ty * 8 + i) * ldc + n0 + tx * 4;
#pragma unroll
        for (int j = 0; j < 4; j++) atomicAdd(Cr + j, acc[i][j]);
    }
}

// ---------------- kernel 1: fused QKV GEMM (split-K=2) -----------------------
__global__ __launch_bounds__(128) void qkv_gemm_kernel(
        const float* __restrict__ x,
        const float* __restrict__ Wq,
        const float* __restrict__ Wk,
        const float* __restrict__ Wv) {
    int n0g = blockIdx.x * GBN;
    int m0  = blockIdx.y * GBM;
    int kb  = blockIdx.z * (C_ / 2);
    const float* B;
    float* Cp;
    int ldb, n0;
    if (n0g < C_)             { B = Wq; Cp = g_q; ldb = C_;   n0 = n0g; }
    else if (n0g < C_ + KVC_) { B = Wk; Cp = g_k; ldb = KVC_; n0 = n0g - C_; }
    else                      { B = Wv; Cp = g_v; ldb = KVC_; n0 = n0g - C_ - KVC_; }
    gemm_tile_atomic(x, C_, B, ldb, Cp, ldb, m0, n0, kb, kb + C_ / 2);
}

// ---------------- kernel 2: RoPE + RMSNorm + head transpose ------------------
__global__ void rope_norm_kernel(const float* __restrict__ cosp,
                                 const float* __restrict__ sinp) {
    int t = blockIdx.x;
    int warp = threadIdx.x >> 5;
    int lane = threadIdx.x & 31;
    float c = cosp[t * HALF_ + lane];
    float s = sinp[t * HALF_ + lane];

    for (int task = warp; task < 24; task += 8) {
        if (task < NH_) {                   // Q head
            int h = task;
            const float* src = g_q + (size_t)t * C_ + h * HD_;
            float x1 = src[lane], x2 = src[lane + HALF_];
            float o1 = x1 * c - x2 * s;
            float o2 = x2 * c + x1 * s;
            float ss = o1 * o1 + o2 * o2;
#pragma unroll
            for (int o = 16; o; o >>= 1) ss += __shfl_xor_sync(0xffffffffu, ss, o);
            float r = rsqrtf(ss * (1.0f / HD_) + 1e-6f);
            float* dst = g_Q + ((size_t)h * T_ + t) * HD_;
            dst[lane] = o1 * r;
            dst[lane + HALF_] = o2 * r;
        } else if (task < NH_ + NKV_) {     // K head
            int h = task - NH_;
            const float* src = g_k + (size_t)t * KVC_ + h * HD_;
            float x1 = src[lane], x2 = src[lane + HALF_];
            float o1 = x1 * c - x2 * s;
            float o2 = x2 * c + x1 * s;
            float ss = o1 * o1 + o2 * o2;
#pragma unroll
            for (int o = 16; o; o >>= 1) ss += __shfl_xor_sync(0xffffffffu, ss, o);
            float r = rsqrtf(ss * (1.0f / HD_) + 1e-6f);
            float* dst = g_K + ((size_t)h * T_ + t) * HD_;
            dst[lane] = o1 * r;
            dst[lane + HALF_] = o2 * r;
        } else {                            // V: plain head-major copy
            int h = task - NH_ - NKV_;
            const float* src = g_v + (size_t)t * KVC_ + h * HD_;
            float* dst = g_V + ((size_t)h * T_ + t) * HD_;
            dst[lane] = src[lane];
            dst[lane + HALF_] = src[lane + HALF_];
        }
    }
}

// ---------------- kernel 3: block-tiled tropical flash attention -------------
// Block = (q-tile pair p, head). Processes q-tiles p and 15-p (32 rows each)
// so every block sees 17 key tiles (load balance). 8 warps, 4 q-rows per warp.
// Score phase: lanes = keys, K transposed in shared (float4, conflict-free).
// PV phase: lanes = dims (d=lane, d=lane+32), V interleaved as float2.
__global__ __launch_bounds__(256) void attn_kernel() {
    __shared__ float  Qs[32][68];         // [row][d] padded
    __shared__ float4 KT4[16][33];        // [d-group][key] padded
    __shared__ float2 Vs2[32][34];        // [key][d-pair] padded

    int h = blockIdx.y;
    int kv = h >> 1;                       // n_rep = 2
    int tid = threadIdx.x;
    int warp = tid >> 5, lane = tid & 31;
    const float* Kb = g_K + (size_t)kv * T_ * HD_;
    const float* Vb = g_V + (size_t)kv * T_ * HD_;

    for (int pass = 0; pass < 2; pass++) {
        int qt = pass ? (15 - blockIdx.x) : blockIdx.x;
        int qbase = qt * 32;
        __syncthreads();                   // protect previous pass's shared reads
#pragma unroll
        for (int i = 0; i < 2; i++) {      // load 32x64 Q tile
            int f = tid + i * 256;
            int r = f >> 4, dg = f & 15;
            float4 qv = *(const float4*)(g_Q + ((size_t)h * T_ + qbase + r) * HD_ + dg * 4);
            *(float4*)&Qs[r][dg * 4] = qv;
        }

        float m[4], l[4], a0[4], a1[4], s[4];
#pragma unroll
        for (int r = 0; r < 4; r++) { m[r] = -1e30f; l[r] = 0.0f; a0[r] = 0.0f; a1[r] = 0.0f; }
        int qi0 = qbase + warp * 4;        // warp's first q row

        for (int j0 = 0; j0 < qbase + 32; j0 += 32) {
            __syncthreads();               // prior tile consumed / Qs stores visible
#pragma unroll
            for (int i = 0; i < 2; i++) {  // load K (transposed) + V (interleaved)
                int f = tid + i * 256;
                int j = f >> 4, dg = f & 15;
                KT4[dg][j] = *(const float4*)(Kb + (size_t)(j0 + j) * HD_ + dg * 4);
                float4 vv = *(const float4*)(Vb + (size_t)(j0 + j) * HD_ + dg * 4);
                int c0 = dg * 4;
                if (c0 < 32) {
                    Vs2[j][c0 + 0].x = vv.x; Vs2[j][c0 + 1].x = vv.y;
                    Vs2[j][c0 + 2].x = vv.z; Vs2[j][c0 + 3].x = vv.w;
                } else {
                    int cc = c0 - 32;
                    Vs2[j][cc + 0].y = vv.x; Vs2[j][cc + 1].y = vv.y;
                    Vs2[j][cc + 2].y = vv.z; Vs2[j][cc + 3].y = vv.w;
                }
            }
            __syncthreads();
            if (j0 > qi0 + 3) continue;    // tile fully masked for this warp

            // --- scores: s[r] = max_d(q[r][d] + k[lane][d]) ---
#pragma unroll
            for (int r = 0; r < 4; r++) s[r] = -1e30f;
#pragma unroll
            for (int dg = 0; dg < 16; dg++) {
                float4 k4 = KT4[dg][lane];
#pragma unroll
                for (int r = 0; r < 4; r++) {
                    float4 q4 = *(const float4*)&Qs[warp * 4 + r][dg * 4];
                    float t0 = fmaxf(q4.x + k4.x, q4.y + k4.y);
                    float t1 = fmaxf(q4.z + k4.z, q4.w + k4.w);
                    s[r] = fmaxf(s[r], fmaxf(t0, t1));
                }
            }
            // --- online softmax + PV per q-row ---
#pragma unroll
            for (int r = 0; r < 4; r++) {
                int qi = qi0 + r;
                if (j0 + lane > qi) s[r] = -1e30f;   // causal mask
                float tm = s[r];
#pragma unroll
                for (int o = 16; o; o >>= 1) tm = fmaxf(tm, __shfl_xor_sync(0xffffffffu, tm, o));
                float mn = fmaxf(m[r], tm);
                float corr = __expf(m[r] - mn);      // exp(-1e30) underflows to 0
                float w = __expf(s[r] - mn);
                m[r] = mn;
                l[r] = l[r] * corr + w;              // per-lane partial sum
                a0[r] *= corr; a1[r] *= corr;
#pragma unroll
                for (int j = 0; j < 32; j++) {
                    float wj = __shfl_sync(0xffffffffu, w, j);
                    float2 v2 = Vs2[j][lane];
                    a0[r] += wj * v2.x;
                    a1[r] += wj * v2.y;
                }
            }
        }
        // --- finalize: reduce l across lanes, normalize, write ---
#pragma unroll
        for (int r = 0; r < 4; r++) {
            float ls = l[r];
#pragma unroll
            for (int o = 16; o; o >>= 1) ls += __shfl_xor_sync(0xffffffffu, ls, o);
            float inv = 1.0f / ls;
            int qi = qi0 + r;
            float* Yp = g_Y + (size_t)qi * C_ + h * HD_;
            Yp[lane] = a0[r] * inv;
            Yp[lane + HALF_] = a1[r] * inv;
        }
    }
}

// ---------------- kernel 4: output projection (split-K=2) --------------------
__global__ __launch_bounds__(128) void proj_gemm_kernel(const float* __restrict__ Wp,
                                                        float* __restrict__ out) {
    int kb = blockIdx.z * (C_ / 2);
    gemm_tile_atomic(g_Y, C_, Wp, C_, out, C_,
                     blockIdx.y * GBM, blockIdx.x * GBN, kb, kb + C_ / 2);
}

// ---------------- launch -----------------------------------------------------
extern "C" void kernel_launch(void* const* d_in, const int* in_sizes, int n_in,
                              void* d_out, int out_size) {
    const float* x    = (const float*)d_in[0];
    const float* cosp = (const float*)d_in[1];
    const float* sinp = (const float*)d_in[2];
    const float* Wq   = (const float*)d_in[3];
    const float* Wk   = (const float*)d_in[4];
    const float* Wv   = (const float*)d_in[5];
    const float* Wp   = (const float*)d_in[6];
    float* out = (float*)d_out;

    // 0) zero accumulation targets (split-K atomics)
    zero_kernel<<<(T_ * C_ + 255) / 256, 256>>>(out);
    // 1) QKV: 512 x 1536, K=768, split-K=2 -> 24x8x2 = 384 blocks
    qkv_gemm_kernel<<<dim3((C_ + 2 * KVC_) / GBN, T_ / GBM, 2), 128>>>(x, Wq, Wk, Wv);
    // 2) RoPE + RMSNorm + transpose to head-major
    rope_norm_kernel<<<T_, 256>>>(cosp, sinp);
    // 3) Tropical flash attention: (8 q-tile pairs) x 12 heads = 96 blocks
    attn_kernel<<<dim3(8, NH_), 256>>>();
    // 4) Projection: 512x768 @ 768x768, split-K=2 -> 12x8x2 = 192 blocks
    proj_gemm_kernel<<<dim3(C_ / GBN, T_ / GBM, 2), 128>>>(Wp, out);
}

// round 8
// speedup vs baseline: 2.2684x; 1.2585x over previous
#include <cuda_runtime.h>
#include <cuda_bf16.h>

// Shapes (compile-time)
#define T_    512
#define C_    768
#define KVC_  384
#define NH_   12
#define NKV_  6
#define HD_   64
#define HALF_ 32
#define NSPLIT 3

// ---------------- scratch (device globals: no allocs allowed) ----------------
__device__ float g_q[T_ * C_];          // x@Wq  (t, h*64+d)
__device__ float g_k[T_ * KVC_];        // x@Wk
__device__ float g_v[T_ * KVC_];        // x@Wv
__device__ float g_Q[NH_ * T_ * HD_];   // head-major, rope+rmsnormed
__device__ float g_K[NKV_ * T_ * HD_];
__device__ float g_V[NKV_ * T_ * HD_];
__device__ float g_Y[T_ * C_];          // attention output (t, h*64+d)
// split-KV attention partials
__device__ float g_Pa[NSPLIT][NH_ * T_ * HD_];   // unnormalized acc (natural dim order)
__device__ float g_Pm[NSPLIT][NH_ * T_];         // running max
__device__ float g_Pl[NSPLIT][NH_ * T_];         // running denom

// ---------------- zero-init for split-K atomic accumulation ------------------
__global__ void zero_kernel(float* out) {
    int i = blockIdx.x * blockDim.x + threadIdx.x;
    if (i < T_ * C_) { g_q[i] = 0.0f; out[i] = 0.0f; }
    if (i < T_ * KVC_) { g_k[i] = 0.0f; g_v[i] = 0.0f; }
}

// ---------------- fp32 GEMM tile: 64x64, BK=16, 128 threads, 8x4 micro -------
#define GBM 64
#define GBN 64
#define GBK 16

__device__ __forceinline__ void gemm_tile_atomic(
        const float* __restrict__ A, int lda,
        const float* __restrict__ B, int ldb,
        float* __restrict__ C, int ldc,
        int m0, int n0, int k_begin, int k_end) {
    __shared__ float As[GBK][GBM + 4];   // transposed A, padded
    __shared__ float Bs[GBK][GBN];

    const int tid = threadIdx.x;
    const int tx = tid & 15;          // 16 col groups * 4 cols
    const int ty = tid >> 4;          // 8 row groups * 8 rows

    float acc[8][4] = {};

    for (int k0 = k_begin; k0 < k_end; k0 += GBK) {
        float4 av[2], bv[2];
#pragma unroll
        for (int i = 0; i < 2; i++) {
            int f = tid + i * 128;
            int ar = f >> 2, ac = (f & 3) * 4;
            av[i] = *(const float4*)(A + (size_t)(m0 + ar) * lda + k0 + ac);
            int br = f >> 4, bc = (f & 15) * 4;
            bv[i] = *(const float4*)(B + (size_t)(k0 + br) * ldb + n0 + bc);
        }
        __syncthreads();
#pragma unroll
        for (int i = 0; i < 2; i++) {
            int f = tid + i * 128;
            int ar = f >> 2, ac = (f & 3) * 4;
            As[ac + 0][ar] = av[i].x;
            As[ac + 1][ar] = av[i].y;
            As[ac + 2][ar] = av[i].z;
            As[ac + 3][ar] = av[i].w;
            int br = f >> 4, bc = (f & 15) * 4;
            *(float4*)&Bs[br][bc] = bv[i];
        }
        __syncthreads();
#pragma unroll
        for (int k = 0; k < GBK; k++) {
            float4 a0 = *(const float4*)&As[k][ty * 8];
            float4 a1 = *(const float4*)&As[k][ty * 8 + 4];
            float4 b  = *(const float4*)&Bs[k][tx * 4];
            acc[0][0] += a0.x * b.x; acc[0][1] += a0.x * b.y; acc[0][2] += a0.x * b.z; acc[0][3] += a0.x * b.w;
            acc[1][0] += a0.y * b.x; acc[1][1] += a0.y * b.y; acc[1][2] += a0.y * b.z; acc[1][3] += a0.y * b.w;
            acc[2][0] += a0.z * b.x; acc[2][1] += a0.z * b.y; acc[2][2] += a0.z * b.z; acc[2][3] += a0.z * b.w;
            acc[3][0] += a0.w * b.x; acc[3][1] += a0.w * b.y; acc[3][2] += a0.w * b.z; acc[3][3] += a0.w * b.w;
            acc[4][0] += a1.x * b.x; acc[4][1] += a1.x * b.y; acc[4][2] += a1.x * b.z; acc[4][3] += a1.x * b.w;
            acc[5][0] += a1.y * b.x; acc[5][1] += a1.y * b.y; acc[5][2] += a1.y * b.z; acc[5][3] += a1.y * b.w;
            acc[6][0] += a1.z * b.x; acc[6][1] += a1.z * b.y; acc[6][2] += a1.z * b.z; acc[6][3] += a1.z * b.w;
            acc[7][0] += a1.w * b.x; acc[7][1] += a1.w * b.y; acc[7][2] += a1.w * b.z; acc[7][3] += a1.w * b.w;
        }
    }

#pragma unroll
    for (int i = 0; i < 8; i++) {
        float* Cr = C + (size_t)(m0 + ty * 8 + i) * ldc + n0 + tx * 4;
#pragma unroll
        for (int j = 0; j < 4; j++) atomicAdd(Cr + j, acc[i][j]);
    }
}

// ---------------- kernel 1: fused QKV GEMM (split-K=2) -----------------------
__global__ __launch_bounds__(128) void qkv_gemm_kernel(
        const float* __restrict__ x,
        const float* __restrict__ Wq,
        const float* __restrict__ Wk,
        const float* __restrict__ Wv) {
    int n0g = blockIdx.x * GBN;
    int m0  = blockIdx.y * GBM;
    int kb  = blockIdx.z * (C_ / 2);
    const float* B;
    float* Cp;
    int ldb, n0;
    if (n0g < C_)             { B = Wq; Cp = g_q; ldb = C_;   n0 = n0g; }
    else if (n0g < C_ + KVC_) { B = Wk; Cp = g_k; ldb = KVC_; n0 = n0g - C_; }
    else                      { B = Wv; Cp = g_v; ldb = KVC_; n0 = n0g - C_ - KVC_; }
    gemm_tile_atomic(x, C_, B, ldb, Cp, ldb, m0, n0, kb, kb + C_ / 2);
}

// ---------------- kernel 2: RoPE + RMSNorm + head transpose ------------------
__global__ void rope_norm_kernel(const float* __restrict__ cosp,
                                 const float* __restrict__ sinp) {
    int t = blockIdx.x;
    int warp = threadIdx.x >> 5;
    int lane = threadIdx.x & 31;
    float c = cosp[t * HALF_ + lane];
    float s = sinp[t * HALF_ + lane];

    for (int task = warp; task < 24; task += 8) {
        if (task < NH_) {                   // Q head
            int h = task;
            const float* src = g_q + (size_t)t * C_ + h * HD_;
            float x1 = src[lane], x2 = src[lane + HALF_];
            float o1 = x1 * c - x2 * s;
            float o2 = x2 * c + x1 * s;
            float ss = o1 * o1 + o2 * o2;
#pragma unroll
            for (int o = 16; o; o >>= 1) ss += __shfl_xor_sync(0xffffffffu, ss, o);
            float r = rsqrtf(ss * (1.0f / HD_) + 1e-6f);
            float* dst = g_Q + ((size_t)h * T_ + t) * HD_;
            dst[lane] = o1 * r;
            dst[lane + HALF_] = o2 * r;
        } else if (task < NH_ + NKV_) {     // K head
            int h = task - NH_;
            const float* src = g_k + (size_t)t * KVC_ + h * HD_;
            float x1 = src[lane], x2 = src[lane + HALF_];
            float o1 = x1 * c - x2 * s;
            float o2 = x2 * c + x1 * s;
            float ss = o1 * o1 + o2 * o2;
#pragma unroll
            for (int o = 16; o; o >>= 1) ss += __shfl_xor_sync(0xffffffffu, ss, o);
            float r = rsqrtf(ss * (1.0f / HD_) + 1e-6f);
            float* dst = g_K + ((size_t)h * T_ + t) * HD_;
            dst[lane] = o1 * r;
            dst[lane + HALF_] = o2 * r;
        } else {                            // V: plain head-major copy
            int h = task - NH_ - NKV_;
            const float* src = g_v + (size_t)t * KVC_ + h * HD_;
            float* dst = g_V + ((size_t)h * T_ + t) * HD_;
            dst[lane] = src[lane];
            dst[lane + HALF_] = src[lane + HALF_];
        }
    }
}

// ---------------- kernel 3: split-KV block-tiled tropical flash attention ----
// Grid (8 q-tile pairs, 12 heads, 3 KV splits). Block handles q-tiles p and
// 15-p (32 rows each); split s processes key tiles s, s+3, s+6, ... Partials
// (m, l, unnormalized acc) go to g_P*; attn_merge combines them.
// PV phase: lane owns dims (2*lane, 2*lane+1), matching the pair-major VsT
// staging; finalize writes Pa in natural dim order.
__global__ __launch_bounds__(256, 2) void attn_kernel() {
    __shared__ float  Qs[32][68];          // [row][d] padded
    __shared__ float4 KT4[16][33];         // [d-group][key] padded
    __shared__ float2 VsT[32][34];         // [dim-pair][key] padded: VsT[p][j] = (V[j][2p], V[j][2p+1])
    __shared__ float4 ws4[8][4][8];        // [warp][r][key-group] staged weights

    int h = blockIdx.y;
    int split = blockIdx.z;
    int kv = h >> 1;                       // n_rep = 2
    int tid = threadIdx.x;
    int warp = tid >> 5, lane = tid & 31;
    const float* Kb = g_K + (size_t)kv * T_ * HD_;
    const float* Vb = g_V + (size_t)kv * T_ * HD_;

    for (int pass = 0; pass < 2; pass++) {
        int qt = pass ? (15 - blockIdx.x) : blockIdx.x;
        int qbase = qt * 32;
        __syncthreads();                   // protect previous pass's shared reads
#pragma unroll
        for (int i = 0; i < 2; i++) {      // load 32x64 Q tile
            int f = tid + i * 256;
            int r = f >> 4, dg = f & 15;
            float4 qv = *(const float4*)(g_Q + ((size_t)h * T_ + qbase + r) * HD_ + dg * 4);
            *(float4*)&Qs[r][dg * 4] = qv;
        }

        float m[4], l[4], a0[4], a1[4], s[4];
#pragma unroll
        for (int r = 0; r < 4; r++) { m[r] = -1e30f; l[r] = 0.0f; a0[r] = 0.0f; a1[r] = 0.0f; }
        int qi0 = qbase + warp * 4;        // warp's first q row

        for (int j0 = split * 32; j0 < qbase + 32; j0 += NSPLIT * 32) {
            __syncthreads();               // prior tile consumed / Qs stores visible
#pragma unroll
            for (int i = 0; i < 2; i++) {  // load K (transposed) + V (pair-major)
                int f = tid + i * 256;
                int j = f >> 4, dg = f & 15;
                KT4[dg][j] = *(const float4*)(Kb + (size_t)(j0 + j) * HD_ + dg * 4);
                float4 vv = *(const float4*)(Vb + (size_t)(j0 + j) * HD_ + dg * 4);
                VsT[dg * 2 + 0][j] = make_float2(vv.x, vv.y);
                VsT[dg * 2 + 1][j] = make_float2(vv.z, vv.w);
            }
            __syncthreads();
            if (j0 > qi0 + 3) continue;    // tile fully masked for this warp

            // --- scores: s[r] = max_d(q[r][d] + k[lane][d]) ---
#pragma unroll
            for (int r = 0; r < 4; r++) s[r] = -1e30f;
#pragma unroll
            for (int dg = 0; dg < 16; dg++) {
                float4 k4 = KT4[dg][lane];
#pragma unroll
                for (int r = 0; r < 4; r++) {
                    float4 q4 = *(const float4*)&Qs[warp * 4 + r][dg * 4];
                    float t0 = fmaxf(q4.x + k4.x, q4.y + k4.y);
                    float t1 = fmaxf(q4.z + k4.z, q4.w + k4.w);
                    s[r] = fmaxf(s[r], fmaxf(t0, t1));
                }
            }
            // --- online softmax bookkeeping + stage weights (lane = key) ---
#pragma unroll
            for (int r = 0; r < 4; r++) {
                int qi = qi0 + r;
                if (j0 + lane > qi) s[r] = -1e30f;   // causal mask
                float tm = s[r];
#pragma unroll
                for (int o = 16; o; o >>= 1) tm = fmaxf(tm, __shfl_xor_sync(0xffffffffu, tm, o));
                float mn = fmaxf(m[r], tm);
                float corr = __expf(m[r] - mn);      // exp(-1e30) underflows to 0
                float w = __expf(s[r] - mn);
                m[r] = mn;
                l[r] = l[r] * corr + w;              // per-lane partial denom
                a0[r] *= corr; a1[r] *= corr;        // corr is lane-uniform
                ((float*)&ws4[warp][r][0])[lane] = w;
            }
            __syncwarp();
            // --- PV: lane = dim pair (2*lane, 2*lane+1), float4 over keys ---
#pragma unroll
            for (int r = 0; r < 4; r++) {
                float acc0 = a0[r], acc1 = a1[r];
#pragma unroll
                for (int jb = 0; jb < 8; jb++) {
                    float4 w4 = ws4[warp][r][jb];                        // broadcast
                    float4 vA = *(const float4*)&VsT[lane][jb * 4];      // keys 4jb, 4jb+1
                    float4 vB = *(const float4*)&VsT[lane][jb * 4 + 2];  // keys 4jb+2, 4jb+3
                    acc0 += w4.x * vA.x; acc1 += w4.x * vA.y;
                    acc0 += w4.y * vA.z; acc1 += w4.y * vA.w;
                    acc0 += w4.z * vB.x; acc1 += w4.z * vB.y;
                    acc0 += w4.w * vB.z; acc1 += w4.w * vB.w;
                }
                a0[r] = acc0; a1[r] = acc1;
            }
        }
        // --- finalize: reduce l across lanes, write split partials ---
        // a0 = dim 2*lane, a1 = dim 2*lane+1 -> write natural dim order.
#pragma unroll
        for (int r = 0; r < 4; r++) {
            float ls = l[r];
#pragma unroll
            for (int o = 16; o; o >>= 1) ls += __shfl_xor_sync(0xffffffffu, ls, o);
            int idx = h * T_ + qi0 + r;
            float* Pa = &g_Pa[split][(size_t)idx * HD_];
            Pa[2 * lane]     = a0[r];
            Pa[2 * lane + 1] = a1[r];
            if (lane == 0) { g_Pm[split][idx] = m[r]; g_Pl[split][idx] = ls; }
        }
    }
}

// ---------------- kernel 3b: merge KV-split partials -------------------------
__global__ void attn_merge_kernel() {
    int gw = (blockIdx.x * blockDim.x + threadIdx.x) >> 5;
    int lane = threadIdx.x & 31;
    if (gw >= NH_ * T_) return;
    int h = gw / T_, qi = gw % T_;
    float m0 = g_Pm[0][gw], m1 = g_Pm[1][gw], m2 = g_Pm[2][gw];
    float mn = fmaxf(m0, fmaxf(m1, m2));
    float w0 = __expf(m0 - mn), w1 = __expf(m1 - mn), w2 = __expf(m2 - mn);
    float l = g_Pl[0][gw] * w0 + g_Pl[1][gw] * w1 + g_Pl[2][gw] * w2;
    float inv = 1.0f / l;
    const float* A0 = &g_Pa[0][(size_t)gw * HD_];
    const float* A1 = &g_Pa[1][(size_t)gw * HD_];
    const float* A2 = &g_Pa[2][(size_t)gw * HD_];
    float y0 = (A0[lane] * w0 + A1[lane] * w1 + A2[lane] * w2) * inv;
    float y1 = (A0[lane + HALF_] * w0 + A1[lane + HALF_] * w1 + A2[lane + HALF_] * w2) * inv;
    float* Yp = g_Y + (size_t)qi * C_ + h * HD_;
    Yp[lane] = y0;
    Yp[lane + HALF_] = y1;
}

// ---------------- kernel 4: output projection (split-K=2) --------------------
__global__ __launch_bounds__(128) void proj_gemm_kernel(const float* __restrict__ Wp,
                                                        float* __restrict__ out) {
    int kb = blockIdx.z * (C_ / 2);
    gemm_tile_atomic(g_Y, C_, Wp, C_, out, C_,
                     blockIdx.y * GBM, blockIdx.x * GBN, kb, kb + C_ / 2);
}

// ---------------- launch -----------------------------------------------------
extern "C" void kernel_launch(void* const* d_in, const int* in_sizes, int n_in,
                              void* d_out, int out_size) {
    const float* x    = (const float*)d_in[0];
    const float* cosp = (const float*)d_in[1];
    const float* sinp = (const float*)d_in[2];
    const float* Wq   = (const float*)d_in[3];
    const float* Wk   = (const float*)d_in[4];
    const float* Wv   = (const float*)d_in[5];
    const float* Wp   = (const float*)d_in[6];
    float* out = (float*)d_out;

    // 0) zero accumulation targets (split-K atomics)
    zero_kernel<<<(T_ * C_ + 255) / 256, 256>>>(out);
    // 1) QKV: 512 x 1536, K=768, split-K=2 -> 384 blocks
    qkv_gemm_kernel<<<dim3((C_ + 2 * KVC_) / GBN, T_ / GBM, 2), 128>>>(x, Wq, Wk, Wv);
    // 2) RoPE + RMSNorm + transpose to head-major
    rope_norm_kernel<<<T_, 256>>>(cosp, sinp);
    // 3) Tropical flash attention: 8 pairs x 12 heads x 3 KV-splits = 288 blocks
    attn_kernel<<<dim3(8, NH_, NSPLIT), 256>>>();
    attn_merge_kernel<<<(NH_ * T_ * 32 + 255) / 256, 256>>>();
    // 4) Projection: 512x768 @ 768x768, split-K=2 -> 192 blocks
    proj_gemm_kernel<<<dim3(C_ / GBN, T_ / GBM, 2), 128>>>(Wp, out);
}

// round 9
// speedup vs baseline: 3.5319x; 1.5570x over previous
#include <cuda_runtime.h>
#include <cuda_fp16.h>
#include <cuda_bf16.h>

// Shapes (compile-time)
#define T_    512
#define C_    768
#define KVC_  384
#define NH_   12
#define NKV_  6
#define HD_   64
#define HALF_ 32
#define NSPLIT 3
#define NQKV  1536        // 768 q + 384 k + 384 v output columns

// ---------------- scratch (device globals: no allocs allowed) ----------------
__device__ __half g_xh[T_ * C_];            // x in fp16
__device__ __half g_Wqkvt[NQKV * C_];       // [n][k] fp16: rows 0-767 Wq^T, 768-1151 Wk^T, 1152-1535 Wv^T
__device__ __half g_Wpt[C_ * C_];           // Wproj^T [n][k] fp16
__device__ float  g_qkv[T_ * NQKV];         // QKV GEMM output (t, n)
__device__ float  g_Q[NH_ * T_ * HD_];      // head-major, rope+rmsnormed
__device__ float  g_K[NKV_ * T_ * HD_];
__device__ float  g_V[NKV_ * T_ * HD_];
__device__ __half g_Yh[T_ * C_];            // attention output in fp16 (t, h*64+d)
// split-KV attention partials
__device__ float g_Pa[NSPLIT][NH_ * T_ * HD_];   // unnormalized acc (natural dim order)
__device__ float g_Pm[NSPLIT][NH_ * T_];         // running max
__device__ float g_Pl[NSPLIT][NH_ * T_];         // running denom

// ---------------- kernel 0a: zero out (proj split-K atomics target) ----------
__global__ void zero_kernel(float* out) {
    int i = blockIdx.x * blockDim.x + threadIdx.x;
    if (i < T_ * C_) out[i] = 0.0f;
}

// ---------------- kernel 0b: convert x to fp16 -------------------------------
__global__ void xconv_kernel(const float* __restrict__ x) {
    int i = blockIdx.x * blockDim.x + threadIdx.x;
    if (i < T_ * C_) g_xh[i] = __float2half(x[i]);
}

// ---------------- kernel 0c: transpose+convert weights to [n][k] fp16 --------
// grid (24 k-tiles, 24 n-tiles, 4 sources), block (32, 8).
__global__ void wtrans_kernel(const float* __restrict__ Wq,
                              const float* __restrict__ Wk,
                              const float* __restrict__ Wv,
                              const float* __restrict__ Wp) {
    __shared__ float tile[32][33];
    const float* W; __half* dst; int ncols;
    switch (blockIdx.z) {
        case 0: W = Wq; ncols = C_;   dst = g_Wqkvt;                 break;
        case 1: W = Wk; ncols = KVC_; dst = g_Wqkvt + 768 * C_;      break;
        case 2: W = Wv; ncols = KVC_; dst = g_Wqkvt + 1152 * C_;     break;
        default: W = Wp; ncols = C_;  dst = g_Wpt;                   break;
    }
    int k0 = blockIdx.x * 32;          // row tile in W (K dim, always 768)
    int n0 = blockIdx.y * 32;          // col tile in W (N dim)
    if (n0 >= ncols) return;
    int tx = threadIdx.x, ty = threadIdx.y;
#pragma unroll
    for (int i = 0; i < 4; i++) {
        int r = ty + i * 8;
        tile[r][tx] = W[(size_t)(k0 + r) * ncols + n0 + tx];
    }
    __syncthreads();
#pragma unroll
    for (int i = 0; i < 4; i++) {
        int r = ty + i * 8;
        dst[(size_t)(n0 + r) * C_ + k0 + tx] = __float2half(tile[tx][r]);
    }
}

// ---------------- fp16 tensor-core GEMM tile ---------------------------------
// C[M,N] = A[M,K](fp16,row) @ Bt[N,K](fp16,row)^T, fp32 accum.
// BM=BN=64, BK=32, 128 threads (4 warps, 2x2), warp tile 32x32 (2m x 4n mma).
#define HBM 64
#define HBN 64
#define HBK 32
#define HSA 40   // smem row stride in halves (conflict-free fragment pattern)

__device__ __forceinline__ void mma16816(float* d, const unsigned* a, const unsigned* b) {
    asm volatile(
        "mma.sync.aligned.m16n8k16.row.col.f32.f16.f16.f32 "
        "{%0,%1,%2,%3}, {%4,%5,%6,%7}, {%8,%9}, {%0,%1,%2,%3};"
        : "+f"(d[0]), "+f"(d[1]), "+f"(d[2]), "+f"(d[3])
        : "r"(a[0]), "r"(a[1]), "r"(a[2]), "r"(a[3]), "r"(b[0]), "r"(b[1]));
}

template<bool ATOMIC>
__device__ __forceinline__ void hgemm_tile(
        const __half* __restrict__ A, int lda,
        const __half* __restrict__ Bt, int ldb,
        float* __restrict__ C, int ldc,
        int m0, int n0, int k_begin, int k_end) {
    __shared__ __half As[HBM][HSA];
    __shared__ __half Bs[HBN][HSA];

    const int tid = threadIdx.x;
    const int w = tid >> 5, lane = tid & 31;
    const int wm = (w >> 1) * 32, wn = (w & 1) * 32;
    const int g = lane >> 2, t = lane & 3;

    float acc[2][4][4] = {};

    for (int k0 = k_begin; k0 < k_end; k0 += HBK) {
        uint4 av[2], bv[2];
#pragma unroll
        for (int i = 0; i < 2; i++) {
            int f = tid + i * 128;
            int r = f >> 2, c8 = (f & 3) * 8;
            av[i] = *(const uint4*)(A + (size_t)(m0 + r) * lda + k0 + c8);
            bv[i] = *(const uint4*)(Bt + (size_t)(n0 + r) * ldb + k0 + c8);
        }
        __syncthreads();   // prior iteration's fragment reads done
#pragma unroll
        for (int i = 0; i < 2; i++) {
            int f = tid + i * 128;
            int r = f >> 2, c8 = (f & 3) * 8;
            *(uint4*)&As[r][c8] = av[i];
            *(uint4*)&Bs[r][c8] = bv[i];
        }
        __syncthreads();
#pragma unroll
        for (int ks = 0; ks < 2; ks++) {
            unsigned a[2][4], b[4][2];
#pragma unroll
            for (int mt = 0; mt < 2; mt++) {
                int r = wm + mt * 16;
                int c = ks * 16 + 2 * t;
                a[mt][0] = *(const unsigned*)&As[r + g][c];
                a[mt][1] = *(const unsigned*)&As[r + g + 8][c];
                a[mt][2] = *(const unsigned*)&As[r + g][c + 8];
                a[mt][3] = *(const unsigned*)&As[r + g + 8][c + 8];
            }
#pragma unroll
            for (int nt = 0; nt < 4; nt++) {
                int r = wn + nt * 8 + g;
                int c = ks * 16 + 2 * t;
                b[nt][0] = *(const unsigned*)&Bs[r][c];
                b[nt][1] = *(const unsigned*)&Bs[r][c + 8];
            }
#pragma unroll
            for (int mt = 0; mt < 2; mt++)
#pragma unroll
                for (int nt = 0; nt < 4; nt++)
                    mma16816(acc[mt][nt], a[mt], b[nt]);
        }
    }

#pragma unroll
    for (int mt = 0; mt < 2; mt++) {
#pragma unroll
        for (int nt = 0; nt < 4; nt++) {
            int row0 = m0 + wm + mt * 16 + g;
            int col  = n0 + wn + nt * 8 + 2 * t;
            if (ATOMIC) {
                atomicAdd(&C[(size_t)row0 * ldc + col],     acc[mt][nt][0]);
                atomicAdd(&C[(size_t)row0 * ldc + col + 1], acc[mt][nt][1]);
                atomicAdd(&C[(size_t)(row0 + 8) * ldc + col],     acc[mt][nt][2]);
                atomicAdd(&C[(size_t)(row0 + 8) * ldc + col + 1], acc[mt][nt][3]);
            } else {
                *(float2*)&C[(size_t)row0 * ldc + col] = make_float2(acc[mt][nt][0], acc[mt][nt][1]);
                *(float2*)&C[(size_t)(row0 + 8) * ldc + col] = make_float2(acc[mt][nt][2], acc[mt][nt][3]);
            }
        }
    }
}

// ---------------- kernel 1: QKV GEMM (fp16 HMMA, direct store) ---------------
__global__ __launch_bounds__(128) void qkv_hgemm_kernel() {
    hgemm_tile<false>(g_xh, C_, g_Wqkvt, C_, g_qkv, NQKV,
                      blockIdx.y * HBM, blockIdx.x * HBN, 0, C_);
}

// ---------------- kernel 2: RoPE + RMSNorm + head transpose ------------------
__global__ void rope_norm_kernel(const float* __restrict__ cosp,
                                 const float* __restrict__ sinp) {
    int t = blockIdx.x;
    int warp = threadIdx.x >> 5;
    int lane = threadIdx.x & 31;
    float c = cosp[t * HALF_ + lane];
    float s = sinp[t * HALF_ + lane];

    for (int task = warp; task < 24; task += 8) {
        if (task < NH_) {                   // Q head
            int h = task;
            const float* src = g_qkv + (size_t)t * NQKV + h * HD_;
            float x1 = src[lane], x2 = src[lane + HALF_];
            float o1 = x1 * c - x2 * s;
            float o2 = x2 * c + x1 * s;
            float ss = o1 * o1 + o2 * o2;
#pragma unroll
            for (int o = 16; o; o >>= 1) ss += __shfl_xor_sync(0xffffffffu, ss, o);
            float r = rsqrtf(ss * (1.0f / HD_) + 1e-6f);
            float* dst = g_Q + ((size_t)h * T_ + t) * HD_;
            dst[lane] = o1 * r;
            dst[lane + HALF_] = o2 * r;
        } else if (task < NH_ + NKV_) {     // K head
            int h = task - NH_;
            const float* src = g_qkv + (size_t)t * NQKV + 768 + h * HD_;
            float x1 = src[lane], x2 = src[lane + HALF_];
            float o1 = x1 * c - x2 * s;
            float o2 = x2 * c + x1 * s;
            float ss = o1 * o1 + o2 * o2;
#pragma unroll
            for (int o = 16; o; o >>= 1) ss += __shfl_xor_sync(0xffffffffu, ss, o);
            float r = rsqrtf(ss * (1.0f / HD_) + 1e-6f);
            float* dst = g_K + ((size_t)h * T_ + t) * HD_;
            dst[lane] = o1 * r;
            dst[lane + HALF_] = o2 * r;
        } else {                            // V: plain head-major copy
            int h = task - NH_ - NKV_;
            const float* src = g_qkv + (size_t)t * NQKV + 1152 + h * HD_;
            float* dst = g_V + ((size_t)h * T_ + t) * HD_;
            dst[lane] = src[lane];
            dst[lane + HALF_] = src[lane + HALF_];
        }
    }
}

// ---------------- kernel 3: split-KV block-tiled tropical flash attention ----
__global__ __launch_bounds__(256, 2) void attn_kernel() {
    __shared__ float  Qs[32][68];          // [row][d] padded
    __shared__ float4 KT4[16][33];         // [d-group][key] padded
    __shared__ float2 VsT[32][34];         // [dim-pair][key]: VsT[p][j] = (V[j][2p], V[j][2p+1])
    __shared__ float4 ws4[8][4][8];        // [warp][r][key-group] staged weights

    int h = blockIdx.y;
    int split = blockIdx.z;
    int kv = h >> 1;                       // n_rep = 2
    int tid = threadIdx.x;
    int warp = tid >> 5, lane = tid & 31;
    const float* Kb = g_K + (size_t)kv * T_ * HD_;
    const float* Vb = g_V + (size_t)kv * T_ * HD_;

    for (int pass = 0; pass < 2; pass++) {
        int qt = pass ? (15 - blockIdx.x) : blockIdx.x;
        int qbase = qt * 32;
        __syncthreads();                   // protect previous pass's shared reads
#pragma unroll
        for (int i = 0; i < 2; i++) {      // load 32x64 Q tile
            int f = tid + i * 256;
            int r = f >> 4, dg = f & 15;
            float4 qv = *(const float4*)(g_Q + ((size_t)h * T_ + qbase + r) * HD_ + dg * 4);
            *(float4*)&Qs[r][dg * 4] = qv;
        }

        float m[4], l[4], a0[4], a1[4], s[4];
#pragma unroll
        for (int r = 0; r < 4; r++) { m[r] = -1e30f; l[r] = 0.0f; a0[r] = 0.0f; a1[r] = 0.0f; }
        int qi0 = qbase + warp * 4;        // warp's first q row

        for (int j0 = split * 32; j0 < qbase + 32; j0 += NSPLIT * 32) {
            __syncthreads();               // prior tile consumed / Qs stores visible
#pragma unroll
            for (int i = 0; i < 2; i++) {  // load K (transposed) + V (pair-major)
                int f = tid + i * 256;
                int j = f >> 4, dg = f & 15;
                KT4[dg][j] = *(const float4*)(Kb + (size_t)(j0 + j) * HD_ + dg * 4);
                float4 vv = *(const float4*)(Vb + (size_t)(j0 + j) * HD_ + dg * 4);
                VsT[dg * 2 + 0][j] = make_float2(vv.x, vv.y);
                VsT[dg * 2 + 1][j] = make_float2(vv.z, vv.w);
            }
            __syncthreads();
            if (j0 > qi0 + 3) continue;    // tile fully masked for this warp

            // --- scores: s[r] = max_d(q[r][d] + k[lane][d]) ---
#pragma unroll
            for (int r = 0; r < 4; r++) s[r] = -1e30f;
#pragma unroll
            for (int dg = 0; dg < 16; dg++) {
                float4 k4 = KT4[dg][lane];
#pragma unroll
                for (int r = 0; r < 4; r++) {
                    float4 q4 = *(const float4*)&Qs[warp * 4 + r][dg * 4];
                    float t0 = fmaxf(q4.x + k4.x, q4.y + k4.y);
                    float t1 = fmaxf(q4.z + k4.z, q4.w + k4.w);
                    s[r] = fmaxf(s[r], fmaxf(t0, t1));
                }
            }
            // --- online softmax bookkeeping + stage weights (lane = key) ---
#pragma unroll
            for (int r = 0; r < 4; r++) {
                int qi = qi0 + r;
                if (j0 + lane > qi) s[r] = -1e30f;   // causal mask
                float tm = s[r];
#pragma unroll
                for (int o = 16; o; o >>= 1) tm = fmaxf(tm, __shfl_xor_sync(0xffffffffu, tm, o));
                float mn = fmaxf(m[r], tm);
                float corr = __expf(m[r] - mn);      // exp(-1e30) underflows to 0
                float w = __expf(s[r] - mn);
                m[r] = mn;
                l[r] = l[r] * corr + w;              // per-lane partial denom
                a0[r] *= corr; a1[r] *= corr;        // corr is lane-uniform
                ((float*)&ws4[warp][r][0])[lane] = w;
            }
            __syncwarp();
            // --- PV: lane = dim pair (2*lane, 2*lane+1), float4 over keys ---
#pragma unroll
            for (int r = 0; r < 4; r++) {
                float acc0 = a0[r], acc1 = a1[r];
#pragma unroll
                for (int jb = 0; jb < 8; jb++) {
                    float4 w4 = ws4[warp][r][jb];                        // broadcast
                    float4 vA = *(const float4*)&VsT[lane][jb * 4];      // keys 4jb, 4jb+1
                    float4 vB = *(const float4*)&VsT[lane][jb * 4 + 2];  // keys 4jb+2, 4jb+3
                    acc0 += w4.x * vA.x; acc1 += w4.x * vA.y;
                    acc0 += w4.y * vA.z; acc1 += w4.y * vA.w;
                    acc0 += w4.z * vB.x; acc1 += w4.z * vB.y;
                    acc0 += w4.w * vB.z; acc1 += w4.w * vB.w;
                }
                a0[r] = acc0; a1[r] = acc1;
            }
        }
        // --- finalize: reduce l across lanes, write split partials ---
        // a0 = dim 2*lane, a1 = dim 2*lane+1 -> natural dim order.
#pragma unroll
        for (int r = 0; r < 4; r++) {
            float ls = l[r];
#pragma unroll
            for (int o = 16; o; o >>= 1) ls += __shfl_xor_sync(0xffffffffu, ls, o);
            int idx = h * T_ + qi0 + r;
            float* Pa = &g_Pa[split][(size_t)idx * HD_];
            Pa[2 * lane]     = a0[r];
            Pa[2 * lane + 1] = a1[r];
            if (lane == 0) { g_Pm[split][idx] = m[r]; g_Pl[split][idx] = ls; }
        }
    }
}

// ---------------- kernel 3b: merge KV-split partials, emit fp16 Y ------------
__global__ void attn_merge_kernel() {
    int gw = (blockIdx.x * blockDim.x + threadIdx.x) >> 5;
    int lane = threadIdx.x & 31;
    if (gw >= NH_ * T_) return;
    int h = gw / T_, qi = gw % T_;
    float m0 = g_Pm[0][gw], m1 = g_Pm[1][gw], m2 = g_Pm[2][gw];
    float mn = fmaxf(m0, fmaxf(m1, m2));
    float w0 = __expf(m0 - mn), w1 = __expf(m1 - mn), w2 = __expf(m2 - mn);
    float l = g_Pl[0][gw] * w0 + g_Pl[1][gw] * w1 + g_Pl[2][gw] * w2;
    float inv = 1.0f / l;
    const float* A0 = &g_Pa[0][(size_t)gw * HD_];
    const float* A1 = &g_Pa[1][(size_t)gw * HD_];
    const float* A2 = &g_Pa[2][(size_t)gw * HD_];
    float y0 = (A0[lane] * w0 + A1[lane] * w1 + A2[lane] * w2) * inv;
    float y1 = (A0[lane + HALF_] * w0 + A1[lane + HALF_] * w1 + A2[lane + HALF_] * w2) * inv;
    __half* Yp = g_Yh + (size_t)qi * C_ + h * HD_;
    Yp[lane] = __float2half(y0);
    Yp[lane + HALF_] = __float2half(y1);
}

// ---------------- kernel 4: output projection (fp16 HMMA, split-K=2) ---------
__global__ __launch_bounds__(128) void proj_hgemm_kernel(float* __restrict__ out) {
    int kb = blockIdx.z * (C_ / 2);
    hgemm_tile<true>(g_Yh, C_, g_Wpt, C_, out, C_,
                     blockIdx.y * HBM, blockIdx.x * HBN, kb, kb + C_ / 2);
}

// ---------------- launch -----------------------------------------------------
extern "C" void kernel_launch(void* const* d_in, const int* in_sizes, int n_in,
                              void* d_out, int out_size) {
    const float* x    = (const float*)d_in[0];
    const float* cosp = (const float*)d_in[1];
    const float* sinp = (const float*)d_in[2];
    const float* Wq   = (const float*)d_in[3];
    const float* Wk   = (const float*)d_in[4];
    const float* Wv   = (const float*)d_in[5];
    const float* Wp   = (const float*)d_in[6];
    float* out = (float*)d_out;

    // 0) zero proj accumulation target; convert x; transpose+convert weights
    zero_kernel<<<(T_ * C_ + 255) / 256, 256>>>(out);
    xconv_kernel<<<(T_ * C_ + 255) / 256, 256>>>(x);
    wtrans_kernel<<<dim3(C_ / 32, C_ / 32, 4), dim3(32, 8)>>>(Wq, Wk, Wv, Wp);
    // 1) QKV: 512 x 1536, K=768 -> 24x8 = 192 blocks (tensor cores)
    qkv_hgemm_kernel<<<dim3(NQKV / HBN, T_ / HBM), 128>>>();
    // 2) RoPE + RMSNorm + transpose to head-major
    rope_norm_kernel<<<T_, 256>>>(cosp, sinp);
    // 3) Tropical flash attention: 8 pairs x 12 heads x 3 KV-splits = 288 blocks
    attn_kernel<<<dim3(8, NH_, NSPLIT), 256>>>();
    attn_merge_kernel<<<(NH_ * T_ * 32 + 255) / 256, 256>>>();
    // 4) Projection: 512x768 @ 768x768, split-K=2 -> 12x8x2 = 192 blocks
    proj_hgemm_kernel<<<dim3(C_ / HBN, T_ / HBM, 2), 128>>>(out);
}